// round 2
// baseline (speedup 1.0000x reference)
#include <cuda_runtime.h>
#include <cuda_bf16.h>

// Problem constants
#define BATCH 4
#define SEQ   2048
#define DIM   1024            // D_IN = D_K = D_V
#define MTOT  (BATCH * SEQ)   // 8192

// Scratch (no cudaMalloc allowed): Q, K, V projections + scores
__device__ float g_Q[(size_t)MTOT * DIM];
__device__ float g_K[(size_t)MTOT * DIM];
__device__ float g_V[(size_t)MTOT * DIM];
__device__ float g_S[(size_t)BATCH * SEQ * SEQ];

// ---------------------------------------------------------------------------
// Tiled fp32 GEMM:  C[m,n] = sum_k A[m,k] * B'[k,n] (+ bias[n])
//   A: row-major [M,K], lda = K
//   BT = true : B row-major [N,K] (ldb = K)  -> B'[k,n] = B[n*K+k]   (x·Wᵀ, Q·Kᵀ)
//   BT = false: B row-major [K,N] (ldb = N)  -> B'[k,n] = B[k*N+n]   (P·V)
// Tile: 128x128x16, 256 threads, 8x8 per-thread microtile.
// ---------------------------------------------------------------------------
template <bool BT>
__global__ __launch_bounds__(256, 2)
void sgemm_kernel(const float* __restrict__ A, const float* __restrict__ B,
                  const float* __restrict__ bias, float* __restrict__ C,
                  int M, int N, int K,
                  long long strideA, long long strideB, long long strideC)
{
    const long long bz = blockIdx.z;
    A += bz * strideA;
    B += bz * strideB;
    C += bz * strideC;

    __shared__ float As[16][132];   // [k][m], +4 pad keeps rows 16B-aligned
    __shared__ float Bs[16][132];   // [k][n]

    const int tid = threadIdx.x;
    const int m0 = blockIdx.y * 128;
    const int n0 = blockIdx.x * 128;

    const int tm = (tid & 15) * 8;  // row offset of this thread's 8x8 tile
    const int tn = (tid >> 4) * 8;  // col offset

    // loader indices for 128x16 tiles stored transposed (A and B when BT)
    const int lrow = tid >> 2;          // 0..63
    const int lk   = (tid & 3) * 4;     // 0,4,8,12

    float acc[8][8];
#pragma unroll
    for (int i = 0; i < 8; ++i)
#pragma unroll
        for (int j = 0; j < 8; ++j) acc[i][j] = 0.f;

    for (int k0 = 0; k0 < K; k0 += 16) {
        // --- load A tile (128 rows x 16 k), store transposed As[k][m] ---
#pragma unroll
        for (int r = 0; r < 2; ++r) {
            const int row = lrow + r * 64;
            float4 v = *(const float4*)&A[(long long)(m0 + row) * K + k0 + lk];
            As[lk + 0][row] = v.x;
            As[lk + 1][row] = v.y;
            As[lk + 2][row] = v.z;
            As[lk + 3][row] = v.w;
        }
        if (BT) {
            // B tile: 128 n-rows x 16 k, store transposed Bs[k][n]
#pragma unroll
            for (int r = 0; r < 2; ++r) {
                const int row = lrow + r * 64;
                float4 v = *(const float4*)&B[(long long)(n0 + row) * K + k0 + lk];
                Bs[lk + 0][row] = v.x;
                Bs[lk + 1][row] = v.y;
                Bs[lk + 2][row] = v.z;
                Bs[lk + 3][row] = v.w;
            }
        } else {
            // B tile: 16 k-rows x 128 n, direct copy Bs[k][n]
            const int kr = tid >> 5;          // 0..7
            const int nc = (tid & 31) * 4;    // 0..124
#pragma unroll
            for (int r = 0; r < 2; ++r) {
                const int kk = kr + r * 8;
                float4 v = *(const float4*)&B[(long long)(k0 + kk) * N + n0 + nc];
                *(float4*)&Bs[kk][nc] = v;
            }
        }
        __syncthreads();

#pragma unroll
        for (int k = 0; k < 16; ++k) {
            float a[8], b[8];
            *(float4*)&a[0] = *(const float4*)&As[k][tm];
            *(float4*)&a[4] = *(const float4*)&As[k][tm + 4];
            *(float4*)&b[0] = *(const float4*)&Bs[k][tn];
            *(float4*)&b[4] = *(const float4*)&Bs[k][tn + 4];
#pragma unroll
            for (int i = 0; i < 8; ++i)
#pragma unroll
                for (int j = 0; j < 8; ++j)
                    acc[i][j] += a[i] * b[j];
        }
        __syncthreads();
    }

    // epilogue (+bias)
    float bvals[8];
#pragma unroll
    for (int j = 0; j < 8; ++j) bvals[j] = bias ? bias[n0 + tn + j] : 0.f;

#pragma unroll
    for (int i = 0; i < 8; ++i) {
        float4 v0, v1;
        v0.x = acc[i][0] + bvals[0];
        v0.y = acc[i][1] + bvals[1];
        v0.z = acc[i][2] + bvals[2];
        v0.w = acc[i][3] + bvals[3];
        v1.x = acc[i][4] + bvals[4];
        v1.y = acc[i][5] + bvals[5];
        v1.z = acc[i][6] + bvals[6];
        v1.w = acc[i][7] + bvals[7];
        float* cp = &C[(long long)(m0 + tm + i) * N + n0 + tn];
        *(float4*)&cp[0] = v0;
        *(float4*)&cp[4] = v1;
    }
}

// ---------------------------------------------------------------------------
// Row softmax over 2048 cols, then scale by norm (post-softmax, per reference).
// One block (256 threads) per row; each thread holds 8 values in registers.
// ---------------------------------------------------------------------------
__global__ __launch_bounds__(256)
void softmax_scale_kernel(float* __restrict__ S, float norm)
{
    float* p = S + (long long)blockIdx.x * SEQ;
    const int t = threadIdx.x;
    __shared__ float red[8];

    float v[8];
    float mx = -1e30f;
#pragma unroll
    for (int i = 0; i < 8; ++i) {
        v[i] = p[t + (i << 8)];
        mx = fmaxf(mx, v[i]);
    }
#pragma unroll
    for (int o = 16; o; o >>= 1) mx = fmaxf(mx, __shfl_xor_sync(0xffffffffu, mx, o));
    if ((t & 31) == 0) red[t >> 5] = mx;
    __syncthreads();
    mx = red[0];
#pragma unroll
    for (int i = 1; i < 8; ++i) mx = fmaxf(mx, red[i]);

    float s = 0.f;
#pragma unroll
    for (int i = 0; i < 8; ++i) {
        v[i] = __expf(v[i] - mx);
        s += v[i];
    }
#pragma unroll
    for (int o = 16; o; o >>= 1) s += __shfl_xor_sync(0xffffffffu, s, o);
    __syncthreads();                 // red reuse
    if ((t & 31) == 0) red[t >> 5] = s;
    __syncthreads();
    s = 0.f;
#pragma unroll
    for (int i = 0; i < 8; ++i) s += red[i];

    const float inv = norm / s;
#pragma unroll
    for (int i = 0; i < 8; ++i) p[t + (i << 8)] = v[i] * inv;
}

// ---------------------------------------------------------------------------
extern "C" void kernel_launch(void* const* d_in, const int* in_sizes, int n_in,
                              void* d_out, int out_size)
{
    (void)in_sizes; (void)n_in; (void)out_size;
    const float* x  = (const float*)d_in[0];
    const float* Wq = (const float*)d_in[1];
    const float* bq = (const float*)d_in[2];
    const float* Wk = (const float*)d_in[3];
    const float* bk = (const float*)d_in[4];
    const float* Wv = (const float*)d_in[5];
    const float* bv = (const float*)d_in[6];
    float* out = (float*)d_out;

    float *Qp, *Kp, *Vp, *Sp;
    cudaGetSymbolAddress((void**)&Qp, g_Q);
    cudaGetSymbolAddress((void**)&Kp, g_K);
    cudaGetSymbolAddress((void**)&Vp, g_V);
    cudaGetSymbolAddress((void**)&Sp, g_S);

    const dim3 blk(256);

    // QKV projections: [8192,1024] x [1024,1024]^T + bias
    const dim3 gproj(DIM / 128, MTOT / 128, 1);
    sgemm_kernel<true><<<gproj, blk>>>(x, Wq, bq, Qp, MTOT, DIM, DIM, 0, 0, 0);
    sgemm_kernel<true><<<gproj, blk>>>(x, Wk, bk, Kp, MTOT, DIM, DIM, 0, 0, 0);
    sgemm_kernel<true><<<gproj, blk>>>(x, Wv, bv, Vp, MTOT, DIM, DIM, 0, 0, 0);

    // scores = Q @ K^T per batch: [2048,1024] x [2048,1024]^T
    const dim3 gsc(SEQ / 128, SEQ / 128, BATCH);
    sgemm_kernel<true><<<gsc, blk>>>(Qp, Kp, nullptr, Sp, SEQ, SEQ, DIM,
                                     (long long)SEQ * DIM, (long long)SEQ * DIM,
                                     (long long)SEQ * SEQ);

    // softmax rows, post-scale by 1/sqrt(D_K) = 1/32
    softmax_scale_kernel<<<BATCH * SEQ, blk>>>(Sp, 0.03125f);

    // out = P @ V per batch: [2048,2048] x [2048,1024]
    const dim3 gout(DIM / 128, SEQ / 128, BATCH);
    sgemm_kernel<false><<<gout, blk>>>(Sp, Vp, nullptr, out, SEQ, DIM, SEQ,
                                       (long long)SEQ * SEQ, (long long)SEQ * DIM,
                                       (long long)SEQ * DIM);
}

// round 5
// speedup vs baseline: 2.1145x; 2.1145x over previous
#include <cuda_runtime.h>
#include <cuda_fp16.h>
#include <cstdint>
#include <cstddef>

#define BATCH 4
#define SEQ   2048
#define DIM   1024
#define MTOT  (BATCH * SEQ)   // 8192

// ---- GEMM tiling ----
#define BM 128
#define BN 128
#define BK 32                 // 32 halves per row per tile
#define RSB 80                // smem row stride bytes (32*2 + 16 pad)
#define TILE_BYTES (128 * RSB)          // 10240 per (array) tile
#define OFF_AH 0
#define OFF_AL (TILE_BYTES)
#define OFF_BH (2 * TILE_BYTES)
#define OFF_BL (3 * TILE_BYTES)
#define STAGE (4 * TILE_BYTES)          // 40960
#define NSTAGE 3
#define SMEM_REQ (NSTAGE * STAGE)       // 122880

// ---- device scratch (fp16 splits + fp32 scores) ----
__device__ __half g_xh[(size_t)MTOT * DIM];
__device__ __half g_xl[(size_t)MTOT * DIM];
__device__ __half g_wqh[(size_t)DIM * DIM];
__device__ __half g_wql[(size_t)DIM * DIM];
__device__ __half g_wkh[(size_t)DIM * DIM];
__device__ __half g_wkl[(size_t)DIM * DIM];
__device__ __half g_wvh[(size_t)DIM * DIM];
__device__ __half g_wvl[(size_t)DIM * DIM];
__device__ __half g_Qh[(size_t)MTOT * DIM];
__device__ __half g_Ql[(size_t)MTOT * DIM];
__device__ __half g_Kh[(size_t)MTOT * DIM];
__device__ __half g_Kl[(size_t)MTOT * DIM];
__device__ __half g_Vth[(size_t)MTOT * DIM];   // [b][v][s] transposed V
__device__ __half g_Vtl[(size_t)MTOT * DIM];
__device__ float  g_S [(size_t)BATCH * SEQ * SEQ];
__device__ __half g_Ph[(size_t)BATCH * SEQ * SEQ];
__device__ __half g_Pl[(size_t)BATCH * SEQ * SEQ];

// ---------------------------------------------------------------------------
__device__ __forceinline__ uint32_t cvta_smem(const void* p) {
    uint32_t r;
    asm("{ .reg .u64 t; cvta.to.shared.u64 t, %1; cvt.u32.u64 %0, t; }"
        : "=r"(r) : "l"(p));
    return r;
}
__device__ __forceinline__ void cpa16(uint32_t d, const void* s) {
    asm volatile("cp.async.cg.shared.global [%0], [%1], 16;" :: "r"(d), "l"(s));
}
__device__ __forceinline__ void cp_commit() {
    asm volatile("cp.async.commit_group;" ::: "memory");
}
__device__ __forceinline__ void ldsm4(uint32_t& r0, uint32_t& r1, uint32_t& r2,
                                      uint32_t& r3, uint32_t addr) {
    asm volatile("ldmatrix.sync.aligned.m8n8.x4.shared.b16 {%0,%1,%2,%3}, [%4];"
                 : "=r"(r0), "=r"(r1), "=r"(r2), "=r"(r3) : "r"(addr));
}
__device__ __forceinline__ void mma16816(float* c, const uint32_t* a,
                                         const uint32_t* b) {
    asm volatile(
        "mma.sync.aligned.m16n8k16.row.col.f32.f16.f16.f32 "
        "{%0,%1,%2,%3}, {%4,%5,%6,%7}, {%8,%9}, {%0,%1,%2,%3};"
        : "+f"(c[0]), "+f"(c[1]), "+f"(c[2]), "+f"(c[3])
        : "r"(a[0]), "r"(a[1]), "r"(a[2]), "r"(a[3]), "r"(b[0]), "r"(b[1]));
}

// ---------------------------------------------------------------------------
// 3xFP16 split GEMM:  C = (Ah+Al) @ (Bh+Bl)^T   (A:[M,K], B:[N,K], both K-major)
// EPI: 0 = fp32 out (no bias), 1 = fp16 hi/lo split out (+bias),
//      2 = transposed fp16 hi/lo split out (+bias) — Vt[b][n][s]
// ---------------------------------------------------------------------------
template <int EPI>
__global__ __launch_bounds__(256, 1)
void hgemm3x_kernel(const __half* __restrict__ Ahg, const __half* __restrict__ Alg,
                    const __half* __restrict__ Bhg, const __half* __restrict__ Blg,
                    const float* __restrict__ bias,
                    float* __restrict__ C0, __half* __restrict__ H0,
                    __half* __restrict__ H1,
                    int N, int K,
                    long long sA, long long sB, long long sC)
{
    extern __shared__ char smem_raw[];
    const uint32_t sb = cvta_smem(smem_raw);

    const int tid  = threadIdx.x;
    const int wid  = tid >> 5;
    const int lane = tid & 31;
    const long long bz = blockIdx.z;

    Ahg += bz * sA;  Alg += bz * sA;
    Bhg += bz * sB;  Blg += bz * sB;

    const int m0 = blockIdx.y * BM;
    const int n0 = blockIdx.x * BN;

    const int wm = (wid & 3) * 32;   // warp row offset (4 warps in m)
    const int wn = (wid >> 2) * 64;  // warp col offset (2 warps in n)

    float c[2][8][4];
#pragma unroll
    for (int mt = 0; mt < 2; ++mt)
#pragma unroll
        for (int nt = 0; nt < 8; ++nt)
#pragma unroll
            for (int i = 0; i < 4; ++i) c[mt][nt][i] = 0.f;

    const int NK = K / BK;

    auto load_stage = [&](int slot, int kc) {
        const uint32_t tb = sb + slot * STAGE;
#pragma unroll
        for (int i = 0; i < 2; ++i) {
            const int ch  = tid + i * 256;          // 0..511
            const int row = ch >> 2;
            const int kcc = (ch & 3) * 8;           // half offset within row
            const uint32_t so = (uint32_t)(row * RSB + kcc * 2);
            const long long ga = (long long)(m0 + row) * K + kc + kcc;
            const long long gb = (long long)(n0 + row) * K + kc + kcc;
            cpa16(tb + OFF_AH + so, Ahg + ga);
            cpa16(tb + OFF_AL + so, Alg + ga);
            cpa16(tb + OFF_BH + so, Bhg + gb);
            cpa16(tb + OFF_BL + so, Blg + gb);
        }
    };

    // prefetch NSTAGE-1 stages
#pragma unroll
    for (int s = 0; s < NSTAGE - 1; ++s) { load_stage(s, s * BK); cp_commit(); }

    // ldmatrix lane address components
    const int a_row = (lane & 15);            // 0..15
    const int a_kof = (lane >> 4) * 8;        // 0 or 8 (halves)
    const int b_row = ((lane >> 4) << 3) + (lane & 7);  // n row within n16 group
    const int b_kof = ((lane >> 3) & 1) * 8;  // 0 or 8

    for (int it = 0; it < NK; ++it) {
        // fill slot (it+2)%3 — distinct from consumed slot it%3 and (it+1)%3
        if (it + NSTAGE - 1 < NK)
            load_stage((it + NSTAGE - 1) % NSTAGE, (it + NSTAGE - 1) * BK);
        cp_commit();
        // all but the 2 newest groups drained => stage 'it' is complete
        asm volatile("cp.async.wait_group 2;" ::: "memory");
        __syncthreads();

        const uint32_t tb = sb + (it % NSTAGE) * STAGE;
#pragma unroll
        for (int ks = 0; ks < 2; ++ks) {
            const int kh = ks * 16;   // half offset of this k16 step
            uint32_t ah[2][4], al[2][4], bh[8][2], bl[8][2];
#pragma unroll
            for (int mt = 0; mt < 2; ++mt) {
                const uint32_t ao = (uint32_t)((wm + mt * 16 + a_row) * RSB
                                               + (kh + a_kof) * 2);
                ldsm4(ah[mt][0], ah[mt][1], ah[mt][2], ah[mt][3], tb + OFF_AH + ao);
                ldsm4(al[mt][0], al[mt][1], al[mt][2], al[mt][3], tb + OFF_AL + ao);
            }
#pragma unroll
            for (int ng = 0; ng < 4; ++ng) {
                const uint32_t bo = (uint32_t)((wn + ng * 16 + b_row) * RSB
                                               + (kh + b_kof) * 2);
                ldsm4(bh[ng*2][0], bh[ng*2][1], bh[ng*2+1][0], bh[ng*2+1][1],
                      tb + OFF_BH + bo);
                ldsm4(bl[ng*2][0], bl[ng*2][1], bl[ng*2+1][0], bl[ng*2+1][1],
                      tb + OFF_BL + bo);
            }
#pragma unroll
            for (int mt = 0; mt < 2; ++mt)
#pragma unroll
                for (int nt = 0; nt < 8; ++nt) {
                    mma16816(c[mt][nt], ah[mt], bh[nt]);
                    mma16816(c[mt][nt], ah[mt], bl[nt]);
                    mma16816(c[mt][nt], al[mt], bh[nt]);
                }
        }
        // reads of slot it%3 done before iteration it+1 refills it
        __syncthreads();
    }

    // ---- epilogue ----
    const int mrow = lane >> 2;          // 0..7
    const int ncol = (lane & 3) * 2;     // 0,2,4,6

#pragma unroll
    for (int mt = 0; mt < 2; ++mt)
#pragma unroll
        for (int nt = 0; nt < 8; ++nt)
#pragma unroll
            for (int half_ = 0; half_ < 2; ++half_) {   // c pairs (0,1) and (2,3)
                const int m = m0 + wm + mt * 16 + mrow + half_ * 8;
                const int n = n0 + wn + nt * 8 + ncol;
                float v0 = c[mt][nt][half_ * 2 + 0];
                float v1 = c[mt][nt][half_ * 2 + 1];
                if (EPI != 0) { v0 += bias[n]; v1 += bias[n + 1]; }

                if (EPI == 0) {
                    float2 v; v.x = v0; v.y = v1;
                    *(float2*)&C0[bz * sC + (size_t)m * N + n] = v;
                } else if (EPI == 1) {
                    __half h0 = __float2half_rn(v0);
                    __half h1 = __float2half_rn(v1);
                    __half l0 = __float2half_rn(v0 - __half2float(h0));
                    __half l1 = __float2half_rn(v1 - __half2float(h1));
                    __half2 hh; hh.x = h0; hh.y = h1;
                    __half2 ll; ll.x = l0; ll.y = l1;
                    *(__half2*)&H0[(size_t)m * N + n] = hh;
                    *(__half2*)&H1[(size_t)m * N + n] = ll;
                } else {
                    const int b = m >> 11;          // SEQ = 2048
                    const int s = m & 2047;
                    const size_t base = (size_t)b * DIM * SEQ + s;
                    __half h0 = __float2half_rn(v0);
                    __half h1 = __float2half_rn(v1);
                    H0[base + (size_t)n * SEQ]       = h0;
                    H0[base + (size_t)(n + 1) * SEQ] = h1;
                    H1[base + (size_t)n * SEQ]       = __float2half_rn(v0 - __half2float(h0));
                    H1[base + (size_t)(n + 1) * SEQ] = __float2half_rn(v1 - __half2float(h1));
                }
            }
}

// ---------------------------------------------------------------------------
// fp32 -> fp16 hi/lo split
// ---------------------------------------------------------------------------
__global__ __launch_bounds__(256)
void split_kernel(const float* __restrict__ in, __half* __restrict__ hi,
                  __half* __restrict__ lo, int n4)
{
    int i = blockIdx.x * 256 + threadIdx.x;
    if (i < n4) {
        float4 v = ((const float4*)in)[i];
        __half h[4], l[4];
        float vv[4] = {v.x, v.y, v.z, v.w};
#pragma unroll
        for (int j = 0; j < 4; ++j) {
            h[j] = __float2half_rn(vv[j]);
            l[j] = __float2half_rn(vv[j] - __half2float(h[j]));
        }
        ((uint2*)hi)[i] = *(uint2*)h;
        ((uint2*)lo)[i] = *(uint2*)l;
    }
}

// ---------------------------------------------------------------------------
// Row softmax over 2048, post-scale by norm, fp16 hi/lo split output
// ---------------------------------------------------------------------------
__global__ __launch_bounds__(256)
void softmax_split_kernel(const float* __restrict__ S, __half* __restrict__ Ph,
                          __half* __restrict__ Pl, float norm)
{
    const float* p = S + (long long)blockIdx.x * SEQ;
    __half* ph = Ph + (long long)blockIdx.x * SEQ;
    __half* pl = Pl + (long long)blockIdx.x * SEQ;
    const int t = threadIdx.x;
    __shared__ float red[8];

    float v[8];
    float mx = -1e30f;
#pragma unroll
    for (int i = 0; i < 8; ++i) {
        v[i] = p[t + (i << 8)];
        mx = fmaxf(mx, v[i]);
    }
#pragma unroll
    for (int o = 16; o; o >>= 1) mx = fmaxf(mx, __shfl_xor_sync(0xffffffffu, mx, o));
    if ((t & 31) == 0) red[t >> 5] = mx;
    __syncthreads();
    mx = red[0];
#pragma unroll
    for (int i = 1; i < 8; ++i) mx = fmaxf(mx, red[i]);

    float s = 0.f;
#pragma unroll
    for (int i = 0; i < 8; ++i) { v[i] = __expf(v[i] - mx); s += v[i]; }
#pragma unroll
    for (int o = 16; o; o >>= 1) s += __shfl_xor_sync(0xffffffffu, s, o);
    __syncthreads();
    if ((t & 31) == 0) red[t >> 5] = s;
    __syncthreads();
    s = 0.f;
#pragma unroll
    for (int i = 0; i < 8; ++i) s += red[i];

    const float inv = norm / s;
#pragma unroll
    for (int i = 0; i < 8; ++i) {
        float ps = v[i] * inv;
        __half h = __float2half_rn(ps);
        ph[t + (i << 8)] = h;
        pl[t + (i << 8)] = __float2half_rn(ps - __half2float(h));
    }
}

// ---------------------------------------------------------------------------
extern "C" void kernel_launch(void* const* d_in, const int* in_sizes, int n_in,
                              void* d_out, int out_size)
{
    (void)in_sizes; (void)n_in; (void)out_size;
    const float* x  = (const float*)d_in[0];
    const float* Wq = (const float*)d_in[1];
    const float* bq = (const float*)d_in[2];
    const float* Wk = (const float*)d_in[3];
    const float* bk = (const float*)d_in[4];
    const float* Wv = (const float*)d_in[5];
    const float* bv = (const float*)d_in[6];
    float* out = (float*)d_out;

    __half *xh, *xl, *wqh, *wql, *wkh, *wkl, *wvh, *wvl;
    __half *Qh, *Ql, *Kh, *Kl, *Vth, *Vtl, *Ph, *Pl;
    float *S;
    cudaGetSymbolAddress((void**)&xh,  g_xh);  cudaGetSymbolAddress((void**)&xl,  g_xl);
    cudaGetSymbolAddress((void**)&wqh, g_wqh); cudaGetSymbolAddress((void**)&wql, g_wql);
    cudaGetSymbolAddress((void**)&wkh, g_wkh); cudaGetSymbolAddress((void**)&wkl, g_wkl);
    cudaGetSymbolAddress((void**)&wvh, g_wvh); cudaGetSymbolAddress((void**)&wvl, g_wvl);
    cudaGetSymbolAddress((void**)&Qh,  g_Qh);  cudaGetSymbolAddress((void**)&Ql,  g_Ql);
    cudaGetSymbolAddress((void**)&Kh,  g_Kh);  cudaGetSymbolAddress((void**)&Kl,  g_Kl);
    cudaGetSymbolAddress((void**)&Vth, g_Vth); cudaGetSymbolAddress((void**)&Vtl, g_Vtl);
    cudaGetSymbolAddress((void**)&S,   g_S);
    cudaGetSymbolAddress((void**)&Ph,  g_Ph);  cudaGetSymbolAddress((void**)&Pl,  g_Pl);

    cudaFuncSetAttribute(hgemm3x_kernel<0>, cudaFuncAttributeMaxDynamicSharedMemorySize, SMEM_REQ);
    cudaFuncSetAttribute(hgemm3x_kernel<1>, cudaFuncAttributeMaxDynamicSharedMemorySize, SMEM_REQ);
    cudaFuncSetAttribute(hgemm3x_kernel<2>, cudaFuncAttributeMaxDynamicSharedMemorySize, SMEM_REQ);

    const dim3 blk(256);

    // split inputs to fp16 hi/lo
    split_kernel<<<(MTOT * DIM / 4 + 255) / 256, blk>>>(x, xh, xl, MTOT * DIM / 4);
    split_kernel<<<(DIM * DIM / 4 + 255) / 256, blk>>>(Wq, wqh, wql, DIM * DIM / 4);
    split_kernel<<<(DIM * DIM / 4 + 255) / 256, blk>>>(Wk, wkh, wkl, DIM * DIM / 4);
    split_kernel<<<(DIM * DIM / 4 + 255) / 256, blk>>>(Wv, wvh, wvl, DIM * DIM / 4);

    // QKV projections: [8192,1024] x [1024,1024]^T + bias
    const dim3 gproj(DIM / BN, MTOT / BM, 1);   // (8, 64)
    hgemm3x_kernel<1><<<gproj, blk, SMEM_REQ>>>(xh, xl, wqh, wql, bq,
                                                nullptr, Qh, Ql, DIM, DIM, 0, 0, 0);
    hgemm3x_kernel<1><<<gproj, blk, SMEM_REQ>>>(xh, xl, wkh, wkl, bk,
                                                nullptr, Kh, Kl, DIM, DIM, 0, 0, 0);
    hgemm3x_kernel<2><<<gproj, blk, SMEM_REQ>>>(xh, xl, wvh, wvl, bv,
                                                nullptr, Vth, Vtl, DIM, DIM, 0, 0, 0);

    // scores = Q @ K^T per batch: [2048,1024] x [2048,1024]^T
    const dim3 gsc(SEQ / BN, SEQ / BM, BATCH);  // (16, 16, 4)
    hgemm3x_kernel<0><<<gsc, blk, SMEM_REQ>>>(Qh, Ql, Kh, Kl, nullptr,
                                              S, nullptr, nullptr, SEQ, DIM,
                                              (long long)SEQ * DIM, (long long)SEQ * DIM,
                                              (long long)SEQ * SEQ);

    // softmax + post-scale 1/32, split fp16 output
    softmax_split_kernel<<<BATCH * SEQ, blk>>>(S, Ph, Pl, 0.03125f);

    // out = P @ Vt^T per batch: [2048,2048] x [1024,2048]^T
    const dim3 gout(DIM / BN, SEQ / BM, BATCH); // (8, 16, 4)
    hgemm3x_kernel<0><<<gout, blk, SMEM_REQ>>>(Ph, Pl, Vth, Vtl, nullptr,
                                               out, nullptr, nullptr, DIM, SEQ,
                                               (long long)SEQ * SEQ, (long long)DIM * SEQ,
                                               (long long)SEQ * DIM);
}

// round 6
// speedup vs baseline: 2.3026x; 1.0889x over previous
#include <cuda_runtime.h>
#include <cuda_fp16.h>
#include <cstdint>
#include <cstddef>

#define BATCH 4
#define SEQ   2048
#define DIM   1024
#define MTOT  (BATCH * SEQ)   // 8192

// lo-residual arrays are stored pre-scaled by LSCALE to keep fp16 products
// out of the subnormal range (f16-accumulator MMAs would flush them).
#define LSCALE 2048.0f
#define ILSCALE (1.0f / 2048.0f)

// ---- GEMM tiling ----
#define BM 128
#define BN 128
#define BK 32                 // 32 halves per row per tile
#define RSB 80                // smem row stride bytes (32*2 + 16 pad)
#define TILE_BYTES (128 * RSB)          // 10240 per (array) tile
#define OFF_AH 0
#define OFF_AL (TILE_BYTES)
#define OFF_BH (2 * TILE_BYTES)
#define OFF_BL (3 * TILE_BYTES)
#define STAGE (4 * TILE_BYTES)          // 40960
#define NSTAGE 3
#define SMEM_REQ (NSTAGE * STAGE)       // 122880

// ---- device scratch ----
__device__ __half g_xh[(size_t)MTOT * DIM];
__device__ __half g_xl[(size_t)MTOT * DIM];
__device__ __half g_wqh[(size_t)DIM * DIM];
__device__ __half g_wql[(size_t)DIM * DIM];
__device__ __half g_wkh[(size_t)DIM * DIM];
__device__ __half g_wkl[(size_t)DIM * DIM];
__device__ __half g_wvh[(size_t)DIM * DIM];
__device__ __half g_wvl[(size_t)DIM * DIM];
__device__ __half g_Qh[(size_t)MTOT * DIM];
__device__ __half g_Ql[(size_t)MTOT * DIM];
__device__ __half g_Kh[(size_t)MTOT * DIM];
__device__ __half g_Kl[(size_t)MTOT * DIM];
__device__ __half g_Vth[(size_t)MTOT * DIM];   // [b][v][s] transposed V
__device__ __half g_Vtl[(size_t)MTOT * DIM];
__device__ float  g_S [(size_t)BATCH * SEQ * SEQ];
__device__ __half g_Ph[(size_t)BATCH * SEQ * SEQ];

struct ProjArgs {
    const __half* bh[3];
    const __half* bl[3];
    const float*  bias[3];
    __half* oh[3];
    __half* ol[3];
};

// ---------------------------------------------------------------------------
__device__ __forceinline__ uint32_t cvta_smem(const void* p) {
    uint32_t r;
    asm("{ .reg .u64 t; cvta.to.shared.u64 t, %1; cvt.u32.u64 %0, t; }"
        : "=r"(r) : "l"(p));
    return r;
}
__device__ __forceinline__ void cpa16(uint32_t d, const void* s) {
    asm volatile("cp.async.cg.shared.global [%0], [%1], 16;" :: "r"(d), "l"(s));
}
__device__ __forceinline__ void cp_commit() {
    asm volatile("cp.async.commit_group;" ::: "memory");
}
__device__ __forceinline__ void ldsm4(uint32_t& r0, uint32_t& r1, uint32_t& r2,
                                      uint32_t& r3, uint32_t addr) {
    asm volatile("ldmatrix.sync.aligned.m8n8.x4.shared.b16 {%0,%1,%2,%3}, [%4];"
                 : "=r"(r0), "=r"(r1), "=r"(r2), "=r"(r3) : "r"(addr));
}
// main term: fp32 accumulate
__device__ __forceinline__ void mma16816(float* c, const uint32_t* a,
                                         const uint32_t* b) {
    asm volatile(
        "mma.sync.aligned.m16n8k16.row.col.f32.f16.f16.f32 "
        "{%0,%1,%2,%3}, {%4,%5,%6,%7}, {%8,%9}, {%0,%1,%2,%3};"
        : "+f"(c[0]), "+f"(c[1]), "+f"(c[2]), "+f"(c[3])
        : "r"(a[0]), "r"(a[1]), "r"(a[2]), "r"(a[3]), "r"(b[0]), "r"(b[1]));
}
// correction terms: fp16 accumulate (values are small, pre-scaled by LSCALE)
__device__ __forceinline__ void mma16816h(uint32_t* c, const uint32_t* a,
                                          const uint32_t* b) {
    asm volatile(
        "mma.sync.aligned.m16n8k16.row.col.f16.f16.f16.f16 "
        "{%0,%1}, {%2,%3,%4,%5}, {%6,%7}, {%0,%1};"
        : "+r"(c[0]), "+r"(c[1])
        : "r"(a[0]), "r"(a[1]), "r"(a[2]), "r"(a[3]), "r"(b[0]), "r"(b[1]));
}

// ---------------------------------------------------------------------------
// Split-fp16 GEMM:  C = A @ B^T  (A:[M,K], B:[N,K], K-major), main fp32-accum
// + (Ah·Bl' [+ Al'·Bh]) fp16-accum corrections, lo arrays pre-scaled LSCALE.
// EPI 0: plain fp32 out (scores / final out)
// EPI 3: fused QKV projection — blockIdx.z picks W/bias/output; z==2 writes
//        transposed split (Vt), z<2 writes row-major split (Q/K).
// TERMS 3: Ah·Bh + Ah·Bl + Al·Bh ;  TERMS 2: Ah·Bh + Ah·Bl (no A-lo at all)
// ---------------------------------------------------------------------------
template <int EPI, int TERMS>
__global__ __launch_bounds__(256, 1)
void hgemm_kernel(const __half* __restrict__ Ahg, const __half* __restrict__ Alg,
                  const __half* __restrict__ Bhg, const __half* __restrict__ Blg,
                  float* __restrict__ C0, ProjArgs pa,
                  int N, int K,
                  long long sA, long long sB, long long sC)
{
    extern __shared__ char smem_raw[];
    const uint32_t sb = cvta_smem(smem_raw);

    const int tid  = threadIdx.x;
    const int wid  = tid >> 5;
    const int lane = tid & 31;
    const long long bz = blockIdx.z;

    const __half* Bh_;
    const __half* Bl_;
    if (EPI == 3) { Bh_ = pa.bh[bz]; Bl_ = pa.bl[bz]; }
    else          { Bh_ = Bhg + bz * sB; Bl_ = Blg + bz * sB; }
    const __half* Ah_ = Ahg + (EPI == 3 ? 0 : bz * sA);
    const __half* Al_ = (TERMS == 3) ? (Alg + (EPI == 3 ? 0 : bz * sA)) : nullptr;

    const int m0 = blockIdx.y * BM;
    const int n0 = blockIdx.x * BN;

    const int wm = (wid & 3) * 32;   // warp row offset (4 warps in m)
    const int wn = (wid >> 2) * 64;  // warp col offset (2 warps in n)

    float c[2][8][4];
    uint32_t cc[2][8][2];            // f16x2 correction accumulators
#pragma unroll
    for (int mt = 0; mt < 2; ++mt)
#pragma unroll
        for (int nt = 0; nt < 8; ++nt) {
#pragma unroll
            for (int i = 0; i < 4; ++i) c[mt][nt][i] = 0.f;
            cc[mt][nt][0] = 0u; cc[mt][nt][1] = 0u;
        }

    const int NK = K / BK;

    auto load_stage = [&](int slot, int kc) {
        const uint32_t tb = sb + slot * STAGE;
#pragma unroll
        for (int i = 0; i < 2; ++i) {
            const int ch  = tid + i * 256;          // 0..511
            const int row = ch >> 2;
            const int kcc = (ch & 3) * 8;           // half offset within row
            const uint32_t so = (uint32_t)(row * RSB + kcc * 2);
            const long long ga = (long long)(m0 + row) * K + kc + kcc;
            const long long gb = (long long)(n0 + row) * K + kc + kcc;
            cpa16(tb + OFF_AH + so, Ah_ + ga);
            if (TERMS == 3) cpa16(tb + OFF_AL + so, Al_ + ga);
            cpa16(tb + OFF_BH + so, Bh_ + gb);
            cpa16(tb + OFF_BL + so, Bl_ + gb);
        }
    };

    // prefetch NSTAGE-1 stages
#pragma unroll
    for (int s = 0; s < NSTAGE - 1; ++s) { load_stage(s, s * BK); cp_commit(); }

    const int a_row = (lane & 15);
    const int a_kof = (lane >> 4) * 8;
    const int b_row = ((lane >> 4) << 3) + (lane & 7);
    const int b_kof = ((lane >> 3) & 1) * 8;

    for (int it = 0; it < NK; ++it) {
        if (it + NSTAGE - 1 < NK)
            load_stage((it + NSTAGE - 1) % NSTAGE, (it + NSTAGE - 1) * BK);
        cp_commit();
        asm volatile("cp.async.wait_group 2;" ::: "memory");
        __syncthreads();

        const uint32_t tb = sb + (it % NSTAGE) * STAGE;
#pragma unroll
        for (int ks = 0; ks < 2; ++ks) {
            const int kh = ks * 16;
            uint32_t ah[2][4], al[2][4], bh[8][2], bl[8][2];
#pragma unroll
            for (int mt = 0; mt < 2; ++mt) {
                const uint32_t ao = (uint32_t)((wm + mt * 16 + a_row) * RSB
                                               + (kh + a_kof) * 2);
                ldsm4(ah[mt][0], ah[mt][1], ah[mt][2], ah[mt][3], tb + OFF_AH + ao);
                if (TERMS == 3)
                    ldsm4(al[mt][0], al[mt][1], al[mt][2], al[mt][3], tb + OFF_AL + ao);
            }
#pragma unroll
            for (int ng = 0; ng < 4; ++ng) {
                const uint32_t bo = (uint32_t)((wn + ng * 16 + b_row) * RSB
                                               + (kh + b_kof) * 2);
                ldsm4(bh[ng*2][0], bh[ng*2][1], bh[ng*2+1][0], bh[ng*2+1][1],
                      tb + OFF_BH + bo);
                ldsm4(bl[ng*2][0], bl[ng*2][1], bl[ng*2+1][0], bl[ng*2+1][1],
                      tb + OFF_BL + bo);
            }
#pragma unroll
            for (int mt = 0; mt < 2; ++mt)
#pragma unroll
                for (int nt = 0; nt < 8; ++nt) {
                    mma16816(c[mt][nt], ah[mt], bh[nt]);
                    mma16816h(cc[mt][nt], ah[mt], bl[nt]);
                    if (TERMS == 3) mma16816h(cc[mt][nt], al[mt], bh[nt]);
                }
        }
        __syncthreads();
    }

    // ---- epilogue ----
    const int mrow = lane >> 2;
    const int ncol = (lane & 3) * 2;
    const float* bias = (EPI == 3) ? pa.bias[bz] : nullptr;

#pragma unroll
    for (int mt = 0; mt < 2; ++mt)
#pragma unroll
        for (int nt = 0; nt < 8; ++nt) {
            __half2 p0 = *(__half2*)&cc[mt][nt][0];
            __half2 p1 = *(__half2*)&cc[mt][nt][1];
            float corr[4] = { __low2float(p0), __high2float(p0),
                              __low2float(p1), __high2float(p1) };
#pragma unroll
            for (int hf = 0; hf < 2; ++hf) {
                const int m = m0 + wm + mt * 16 + mrow + hf * 8;
                const int n = n0 + wn + nt * 8 + ncol;
                float v0 = c[mt][nt][hf * 2 + 0] + corr[hf * 2 + 0] * ILSCALE;
                float v1 = c[mt][nt][hf * 2 + 1] + corr[hf * 2 + 1] * ILSCALE;

                if (EPI == 0) {
                    float2 v; v.x = v0; v.y = v1;
                    *(float2*)&C0[bz * sC + (size_t)m * N + n] = v;
                } else {
                    v0 += bias[n]; v1 += bias[n + 1];
                    __half h0 = __float2half_rn(v0);
                    __half h1 = __float2half_rn(v1);
                    __half l0 = __float2half_rn((v0 - __half2float(h0)) * LSCALE);
                    __half l1 = __float2half_rn((v1 - __half2float(h1)) * LSCALE);
                    if (bz < 2) {
                        __half2 hh; hh.x = h0; hh.y = h1;
                        __half2 ll; ll.x = l0; ll.y = l1;
                        *(__half2*)&pa.oh[bz][(size_t)m * N + n] = hh;
                        *(__half2*)&pa.ol[bz][(size_t)m * N + n] = ll;
                    } else {
                        const int b = m >> 11;          // SEQ = 2048
                        const int s = m & 2047;
                        const size_t base = (size_t)b * DIM * SEQ + s;
                        pa.oh[2][base + (size_t)n * SEQ]       = h0;
                        pa.oh[2][base + (size_t)(n + 1) * SEQ] = h1;
                        pa.ol[2][base + (size_t)n * SEQ]       = l0;
                        pa.ol[2][base + (size_t)(n + 1) * SEQ] = l1;
                    }
                }
            }
        }
}

// ---------------------------------------------------------------------------
// fp32 -> fp16 hi + scaled-lo split (x)
// ---------------------------------------------------------------------------
__global__ __launch_bounds__(256)
void split_kernel(const float* __restrict__ in, __half* __restrict__ hi,
                  __half* __restrict__ lo, int n4)
{
    int i = blockIdx.x * 256 + threadIdx.x;
    if (i < n4) {
        float4 v = ((const float4*)in)[i];
        __half h[4], l[4];
        float vv[4] = {v.x, v.y, v.z, v.w};
#pragma unroll
        for (int j = 0; j < 4; ++j) {
            h[j] = __float2half_rn(vv[j]);
            l[j] = __float2half_rn((vv[j] - __half2float(h[j])) * LSCALE);
        }
        ((uint2*)hi)[i] = *(uint2*)h;
        ((uint2*)lo)[i] = *(uint2*)l;
    }
}

// fused W splits: z picks which weight matrix
__global__ __launch_bounds__(256)
void wsplit_kernel(const float* __restrict__ s0, const float* __restrict__ s1,
                   const float* __restrict__ s2,
                   __half* __restrict__ h0, __half* __restrict__ l0,
                   __half* __restrict__ h1, __half* __restrict__ l1,
                   __half* __restrict__ h2, __half* __restrict__ l2, int n4)
{
    const int z = blockIdx.z;
    const float* in = z == 0 ? s0 : z == 1 ? s1 : s2;
    __half* hi = z == 0 ? h0 : z == 1 ? h1 : h2;
    __half* lo = z == 0 ? l0 : z == 1 ? l1 : l2;
    int i = blockIdx.x * 256 + threadIdx.x;
    if (i < n4) {
        float4 v = ((const float4*)in)[i];
        __half h[4], l[4];
        float vv[4] = {v.x, v.y, v.z, v.w};
#pragma unroll
        for (int j = 0; j < 4; ++j) {
            h[j] = __float2half_rn(vv[j]);
            l[j] = __float2half_rn((vv[j] - __half2float(h[j])) * LSCALE);
        }
        ((uint2*)hi)[i] = *(uint2*)h;
        ((uint2*)lo)[i] = *(uint2*)l;
    }
}

// ---------------------------------------------------------------------------
// Row softmax over 2048, post-scale by norm, fp16 hi output only
// ---------------------------------------------------------------------------
__global__ __launch_bounds__(256)
void softmax_kernel(const float* __restrict__ S, __half* __restrict__ Ph,
                    float norm)
{
    const float* p = S + (long long)blockIdx.x * SEQ;
    __half* ph = Ph + (long long)blockIdx.x * SEQ;
    const int t = threadIdx.x;
    __shared__ float red[8];

    float v[8];
    float mx = -1e30f;
#pragma unroll
    for (int i = 0; i < 8; ++i) {
        v[i] = p[t + (i << 8)];
        mx = fmaxf(mx, v[i]);
    }
#pragma unroll
    for (int o = 16; o; o >>= 1) mx = fmaxf(mx, __shfl_xor_sync(0xffffffffu, mx, o));
    if ((t & 31) == 0) red[t >> 5] = mx;
    __syncthreads();
    mx = red[0];
#pragma unroll
    for (int i = 1; i < 8; ++i) mx = fmaxf(mx, red[i]);

    float s = 0.f;
#pragma unroll
    for (int i = 0; i < 8; ++i) { v[i] = __expf(v[i] - mx); s += v[i]; }
#pragma unroll
    for (int o = 16; o; o >>= 1) s += __shfl_xor_sync(0xffffffffu, s, o);
    __syncthreads();
    if ((t & 31) == 0) red[t >> 5] = s;
    __syncthreads();
    s = 0.f;
#pragma unroll
    for (int i = 0; i < 8; ++i) s += red[i];

    const float inv = norm / s;
#pragma unroll
    for (int i = 0; i < 8; ++i)
        ph[t + (i << 8)] = __float2half_rn(v[i] * inv);
}

// ---------------------------------------------------------------------------
extern "C" void kernel_launch(void* const* d_in, const int* in_sizes, int n_in,
                              void* d_out, int out_size)
{
    (void)in_sizes; (void)n_in; (void)out_size;
    const float* x  = (const float*)d_in[0];
    const float* Wq = (const float*)d_in[1];
    const float* bq = (const float*)d_in[2];
    const float* Wk = (const float*)d_in[3];
    const float* bk = (const float*)d_in[4];
    const float* Wv = (const float*)d_in[5];
    const float* bv = (const float*)d_in[6];
    float* out = (float*)d_out;

    __half *xh, *xl, *wqh, *wql, *wkh, *wkl, *wvh, *wvl;
    __half *Qh, *Ql, *Kh, *Kl, *Vth, *Vtl, *Ph;
    float *S;
    cudaGetSymbolAddress((void**)&xh,  g_xh);  cudaGetSymbolAddress((void**)&xl,  g_xl);
    cudaGetSymbolAddress((void**)&wqh, g_wqh); cudaGetSymbolAddress((void**)&wql, g_wql);
    cudaGetSymbolAddress((void**)&wkh, g_wkh); cudaGetSymbolAddress((void**)&wkl, g_wkl);
    cudaGetSymbolAddress((void**)&wvh, g_wvh); cudaGetSymbolAddress((void**)&wvl, g_wvl);
    cudaGetSymbolAddress((void**)&Qh,  g_Qh);  cudaGetSymbolAddress((void**)&Ql,  g_Ql);
    cudaGetSymbolAddress((void**)&Kh,  g_Kh);  cudaGetSymbolAddress((void**)&Kl,  g_Kl);
    cudaGetSymbolAddress((void**)&Vth, g_Vth); cudaGetSymbolAddress((void**)&Vtl, g_Vtl);
    cudaGetSymbolAddress((void**)&S,   g_S);
    cudaGetSymbolAddress((void**)&Ph,  g_Ph);

    cudaFuncSetAttribute(hgemm_kernel<0,3>, cudaFuncAttributeMaxDynamicSharedMemorySize, SMEM_REQ);
    cudaFuncSetAttribute(hgemm_kernel<0,2>, cudaFuncAttributeMaxDynamicSharedMemorySize, SMEM_REQ);
    cudaFuncSetAttribute(hgemm_kernel<3,3>, cudaFuncAttributeMaxDynamicSharedMemorySize, SMEM_REQ);

    const dim3 blk(256);
    ProjArgs pa;
    pa.bh[0] = wqh; pa.bh[1] = wkh; pa.bh[2] = wvh;
    pa.bl[0] = wql; pa.bl[1] = wkl; pa.bl[2] = wvl;
    pa.bias[0] = bq; pa.bias[1] = bk; pa.bias[2] = bv;
    pa.oh[0] = Qh; pa.oh[1] = Kh; pa.oh[2] = Vth;
    pa.ol[0] = Ql; pa.ol[1] = Kl; pa.ol[2] = Vtl;
    ProjArgs pz{};   // unused for non-projection GEMMs

    // 0: split x
    split_kernel<<<MTOT * DIM / 4 / 256, blk>>>(x, xh, xl, MTOT * DIM / 4);
    // 1: split all three weight matrices (fused via z)
    wsplit_kernel<<<dim3(DIM * DIM / 4 / 256, 1, 3), blk>>>(
        Wq, Wk, Wv, wqh, wql, wkh, wkl, wvh, wvl, DIM * DIM / 4);

    // 2: fused QKV projections: z in {Q, K, V}
    hgemm_kernel<3,3><<<dim3(DIM / BN, MTOT / BM, 3), blk, SMEM_REQ>>>(
        xh, xl, nullptr, nullptr, nullptr, pa, DIM, DIM, 0, 0, 0);

    // 3: scores = Q @ K^T per batch
    hgemm_kernel<0,3><<<dim3(SEQ / BN, SEQ / BM, BATCH), blk, SMEM_REQ>>>(
        Qh, Ql, Kh, Kl, S, pz, SEQ, DIM,
        (long long)SEQ * DIM, (long long)SEQ * DIM, (long long)SEQ * SEQ);

    // 4: softmax + post-scale 1/32
    softmax_kernel<<<BATCH * SEQ, blk>>>(S, Ph, 0.03125f);

    // 5: out = P @ Vt^T per batch (2-term: Ph·Vh + Ph·Vl)
    hgemm_kernel<0,2><<<dim3(DIM / BN, SEQ / BM, BATCH), blk, SMEM_REQ>>>(
        Ph, nullptr, Vth, Vtl, out, pz, DIM, SEQ,
        (long long)SEQ * SEQ, (long long)DIM * SEQ, (long long)SEQ * DIM);
}